// round 9
// baseline (speedup 1.0000x reference)
#include <cuda_runtime.h>
#include <cuda_bf16.h>
#include <cuda_fp16.h>
#include <math.h>

#define MAXN 50048           // divisible by 16
#define MAXNO (MAXN + 16)    // offs row stride, keeps slice-1 16B-aligned
#define MAXE 1600000

// ---------------- per-slice device scratch (static; no allocations) ----------------
__device__ __align__(16) float  g_dinv[2][MAXN];
__device__ __align__(16) int    g_deg[2][MAXN];
__device__ __align__(16) int    g_offs[2][MAXNO];
__device__ __align__(16) int    g_cursor[2][MAXN];
__device__ __align__(16) int    g_csr[2][MAXE];
__device__ __align__(16) __half g_m[2][(size_t)MAXN * 128];     // fp16, pre-scaled by dinv[row]
__device__ __align__(16) float  g_agg0[2][(size_t)MAXN * 64];
__device__ __align__(16) float  g_agg1[2][(size_t)MAXN * 128];
__device__ __align__(16) float  g_proj[2][(size_t)MAXN * 128];
__device__ __align__(16) float  g_stats0[2][128];
__device__ __align__(16) float  g_stats1[2][256];
__device__ __align__(16) float  g_ab0[2][128];
__device__ __align__(16) float  g_ab1[2][256];
__device__ __align__(16) float  g_hfc[(size_t)MAXN * 128];

// ---------------- static streams / events (host-side, created at load) ----------------
static cudaStream_t g_str[4];
static cudaEvent_t  g_ev[12];
static int g_init_streams = []() {
    for (int i = 0; i < 4; i++) cudaStreamCreateWithFlags(&g_str[i], cudaStreamNonBlocking);
    for (int i = 0; i < 12; i++) cudaEventCreateWithFlags(&g_ev[i], cudaEventDisableTiming);
    return 0;
}();

// nan_to_num(nan=0, posinf=100, neginf=-100)
__device__ __forceinline__ float san(float v) {
    if (isnan(v)) return 0.f;
    if (isinf(v)) return v > 0.f ? 100.f : -100.f;
    return v;
}

__device__ __forceinline__ unsigned h2u(__half2 h) { return *(unsigned*)&h; }

// m16n8k16 f16xf16 -> f32 accumulate
__device__ __forceinline__ void mma16816(float* c, const unsigned* a, unsigned b0, unsigned b1) {
    asm volatile(
        "mma.sync.aligned.m16n8k16.row.col.f32.f16.f16.f32 "
        "{%0,%1,%2,%3}, {%4,%5,%6,%7}, {%8,%9}, {%0,%1,%2,%3};"
        : "+f"(c[0]), "+f"(c[1]), "+f"(c[2]), "+f"(c[3])
        : "r"(a[0]), "r"(a[1]), "r"(a[2]), "r"(a[3]), "r"(b0), "r"(b1));
}

// ---------------- degree ----------------
__global__ void deg_kernel(const int* __restrict__ col, int* __restrict__ deg, int E) {
    int e = blockIdx.x * blockDim.x + threadIdx.x;
    if (e < E) atomicAdd(&deg[col[e]], 1);
}

// single-block exclusive scan (x4 vectorized) -> offs/cursor + fused dinv = rsqrt(deg)
__global__ void scan_kernel(const int* __restrict__ deg, int* __restrict__ offs,
                            int* __restrict__ cursor, float* __restrict__ dinv, int n) {
    __shared__ int wsum[32];
    __shared__ int carry_s;
    int tid = threadIdx.x;
    int lane = tid & 31, wid = tid >> 5;
    if (tid == 0) carry_s = 0;
    __syncthreads();
    int nIter = (n + 4095) >> 12;
    for (int it = 0; it < nIter; it++) {
        int i0 = (it << 12) + tid * 4;
        int v0 = 0, v1 = 0, v2 = 0, v3 = 0;
        if (i0 + 3 < n) {
            int4 t = *(const int4*)(deg + i0);
            v0 = t.x; v1 = t.y; v2 = t.z; v3 = t.w;
        } else {
            if (i0 < n)     v0 = deg[i0];
            if (i0 + 1 < n) v1 = deg[i0 + 1];
            if (i0 + 2 < n) v2 = deg[i0 + 2];
            if (i0 + 3 < n) v3 = deg[i0 + 3];
        }
        int s = v0 + v1 + v2 + v3;
        int x = s;
        #pragma unroll
        for (int off = 1; off < 32; off <<= 1) {
            int y = __shfl_up_sync(0xffffffffu, x, off);
            if (lane >= off) x += y;
        }
        if (lane == 31) wsum[wid] = x;
        __syncthreads();
        if (wid == 0) {
            int w = wsum[lane];
            #pragma unroll
            for (int off = 1; off < 32; off <<= 1) {
                int y = __shfl_up_sync(0xffffffffu, w, off);
                if (lane >= off) w += y;
            }
            wsum[lane] = w;
        }
        __syncthreads();
        int pre = (wid > 0) ? wsum[wid - 1] : 0;
        int total = wsum[31];
        int e0 = carry_s + pre + x - s;
        int o1 = e0 + v0, o2 = o1 + v1, o3 = o2 + v2;
        if (i0 + 3 < n) {
            *(int4*)(offs + i0)   = make_int4(e0, o1, o2, o3);
            *(int4*)(cursor + i0) = make_int4(e0, o1, o2, o3);
            float4 dv = make_float4(v0 > 0 ? rsqrtf((float)v0) : 0.f,
                                    v1 > 0 ? rsqrtf((float)v1) : 0.f,
                                    v2 > 0 ? rsqrtf((float)v2) : 0.f,
                                    v3 > 0 ? rsqrtf((float)v3) : 0.f);
            *(float4*)(dinv + i0) = dv;
        } else {
            int oo[4] = {e0, o1, o2, o3};
            int vv[4] = {v0, v1, v2, v3};
            for (int j = 0; j < 4; j++) {
                if (i0 + j < n) {
                    offs[i0 + j] = oo[j];
                    cursor[i0 + j] = oo[j];
                    dinv[i0 + j] = vv[j] > 0 ? rsqrtf((float)vv[j]) : 0.f;
                }
            }
        }
        __syncthreads();
        if (tid == 0) carry_s += total;
        __syncthreads();
    }
    if (tid == 0) offs[n] = carry_s;
}

__global__ void csr_fill_kernel(const int* __restrict__ row, const int* __restrict__ col,
                                int* __restrict__ cursor, int* __restrict__ csr, int E) {
    int e = blockIdx.x * blockDim.x + threadIdx.x;
    if (e < E) {
        int pos = atomicAdd(&cursor[col[e]], 1);
        csr[pos] = row[e];
    }
}

// ================= HMMA GEMM: C[n,NOUT] = A'[n,64] @ B[64,NOUT] =================
// PRO: 0 = raw A; 1 = h1 epilogue: san(relu(ab[k]*A+ab[64+k]) + X)
// STO: 0 = fp16 * rs[row]; 1 = fp32
template <int NOUT, int PRO, int STO>
__global__ __launch_bounds__(256) void hgemm_kernel(const float* __restrict__ A,
                                                    const float* __restrict__ X,
                                                    const float* __restrict__ ab,
                                                    const float* __restrict__ B,
                                                    const float* __restrict__ rs,
                                                    void* __restrict__ C, int n) {
    constexpr int ASTR = 72;          // halves per A row
    constexpr int BSTR = NOUT + 8;    // words per k-pair
    __shared__ __half  As[128 * ASTR];
    __shared__ unsigned Bs[32 * BSTR];

    int tid = threadIdx.x;
    int row0 = blockIdx.x * 128;

    #pragma unroll
    for (int i = 0; i < 16; i++) {
        int idx = tid + 256 * i;
        int r = idx >> 5, kp = idx & 31;
        float v0 = 0.f, v1 = 0.f;
        if (row0 + r < n) {
            unsigned o = (unsigned)(row0 + r) * 64u + kp * 2;
            if (PRO == 1) {
                float2 av = *(const float2*)&A[o];
                float2 xv = *(const float2*)&X[o];
                float t0 = fmaf(ab[kp * 2], av.x, ab[64 + kp * 2]);
                float t1 = fmaf(ab[kp * 2 + 1], av.y, ab[64 + kp * 2 + 1]);
                v0 = san(fmaxf(t0, 0.f) + xv.x);
                v1 = san(fmaxf(t1, 0.f) + xv.y);
            } else {
                float2 av = *(const float2*)&A[o];
                v0 = av.x; v1 = av.y;
            }
        }
        *(unsigned*)&As[r * ASTR + kp * 2] = h2u(__floats2half2_rn(v0, v1));
    }
    constexpr int BW = (32 * NOUT) / 256;
    #pragma unroll
    for (int i = 0; i < BW; i++) {
        int idx = tid + 256 * i;
        int kp = idx / NOUT, nn = idx % NOUT;
        Bs[kp * BSTR + nn] = h2u(__floats2half2_rn(B[(2 * kp) * NOUT + nn],
                                                   B[(2 * kp + 1) * NOUT + nn]));
    }
    __syncthreads();

    int warp = tid >> 5, lane = tid & 31;
    constexpr int NT = NOUT / 16;
    int wr = warp >> 1, wc = warp & 1;
    int rbase = wr * 32, nbase = wc * (NOUT / 2);
    int g = lane >> 2, q = lane & 3;

    float acc[2][NT][4];
    #pragma unroll
    for (int mt = 0; mt < 2; mt++)
        #pragma unroll
        for (int nt = 0; nt < NT; nt++)
            #pragma unroll
            for (int e = 0; e < 4; e++) acc[mt][nt][e] = 0.f;

    #pragma unroll
    for (int kk = 0; kk < 4; kk++) {
        unsigned a[2][4];
        #pragma unroll
        for (int mt = 0; mt < 2; mt++) {
            const __half* ap = &As[(rbase + mt * 16 + g) * ASTR + kk * 16 + q * 2];
            a[mt][0] = *(const unsigned*)ap;
            a[mt][1] = *(const unsigned*)(ap + 8 * ASTR);
            a[mt][2] = *(const unsigned*)(ap + 8);
            a[mt][3] = *(const unsigned*)(ap + 8 * ASTR + 8);
        }
        int kp = kk * 8 + q;
        #pragma unroll
        for (int nt = 0; nt < NT; nt++) {
            int nn = nbase + nt * 8 + g;
            unsigned b0 = Bs[kp * BSTR + nn];
            unsigned b1 = Bs[(kp + 4) * BSTR + nn];
            mma16816(acc[0][nt], a[0], b0, b1);
            mma16816(acc[1][nt], a[1], b0, b1);
        }
    }

    #pragma unroll
    for (int mt = 0; mt < 2; mt++) {
        #pragma unroll
        for (int h = 0; h < 2; h++) {
            int r = row0 + rbase + mt * 16 + g + h * 8;
            if (r < n) {
                float sc = (STO == 0) ? rs[r] : 1.f;
                #pragma unroll
                for (int nt = 0; nt < NT; nt++) {
                    float c0 = acc[mt][nt][h * 2], c1 = acc[mt][nt][h * 2 + 1];
                    int col = nbase + nt * 8 + q * 2;
                    if (STO == 0) {
                        *(unsigned*)&((__half*)C)[(unsigned)r * NOUT + col] =
                            h2u(__floats2half2_rn(c0 * sc, c1 * sc));
                    } else {
                        *(float2*)&((float*)C)[(unsigned)r * NOUT + col] = make_float2(c0, c1);
                    }
                }
            }
        }
    }
}

// ================= FC1 (HMMA): H = relu(concat(out0,out1)[n,256] @ W[256,128] + b) ======
__global__ __launch_bounds__(256) void hfc1_kernel(const float* __restrict__ agg0,
                                                   const float* __restrict__ proj0,
                                                   const float* __restrict__ ab_0,
                                                   const float* __restrict__ agg1,
                                                   const float* __restrict__ proj1,
                                                   const float* __restrict__ ab_1,
                                                   const float* __restrict__ B,
                                                   const float* __restrict__ bias,
                                                   float* __restrict__ H, int n) {
    constexpr int ASTR = 72;
    constexpr int BSTR = 136;
    __shared__ __half  As[128 * ASTR];
    __shared__ unsigned Bs[32 * BSTR];

    int tid = threadIdx.x;
    int row0 = blockIdx.x * 128;
    int warp = tid >> 5, lane = tid & 31;
    int wr = warp >> 1, wc = warp & 1;
    int rbase = wr * 32, nbase = wc * 64;
    int g = lane >> 2, q = lane & 3;

    float acc[2][8][4];
    #pragma unroll
    for (int mt = 0; mt < 2; mt++)
        #pragma unroll
        for (int nt = 0; nt < 8; nt++)
            #pragma unroll
            for (int e = 0; e < 4; e++) acc[mt][nt][e] = 0.f;

    for (int c = 0; c < 4; c++) {
        __syncthreads();
        const float* agg = (c < 2) ? agg0 : agg1;
        const float* prj = (c < 2) ? proj0 : proj1;
        const float* ab  = (c < 2) ? ab_0 : ab_1;
        int kbase = (c & 1) * 64;
        #pragma unroll
        for (int i = 0; i < 16; i++) {
            int idx = tid + 256 * i;
            int r = idx >> 5, kp = idx & 31;
            float v0 = 0.f, v1 = 0.f;
            if (row0 + r < n) {
                int ch = kbase + kp * 2;
                unsigned o = (unsigned)(row0 + r) * 128u + ch;
                float2 av = *(const float2*)&agg[o];
                float2 pv = *(const float2*)&prj[o];
                v0 = san(fmaf(ab[ch], av.x, ab[128 + ch]) + pv.x);
                v1 = san(fmaf(ab[ch + 1], av.y, ab[128 + ch + 1]) + pv.y);
            }
            *(unsigned*)&As[r * ASTR + kp * 2] = h2u(__floats2half2_rn(v0, v1));
        }
        const float* Bc = B + c * 64 * 128;
        #pragma unroll
        for (int i = 0; i < 16; i++) {
            int idx = tid + 256 * i;
            int kp = idx >> 7, nn = idx & 127;
            Bs[kp * BSTR + nn] = h2u(__floats2half2_rn(Bc[(2 * kp) * 128 + nn],
                                                       Bc[(2 * kp + 1) * 128 + nn]));
        }
        __syncthreads();

        #pragma unroll
        for (int kk = 0; kk < 4; kk++) {
            unsigned a[2][4];
            #pragma unroll
            for (int mt = 0; mt < 2; mt++) {
                const __half* ap = &As[(rbase + mt * 16 + g) * ASTR + kk * 16 + q * 2];
                a[mt][0] = *(const unsigned*)ap;
                a[mt][1] = *(const unsigned*)(ap + 8 * ASTR);
                a[mt][2] = *(const unsigned*)(ap + 8);
                a[mt][3] = *(const unsigned*)(ap + 8 * ASTR + 8);
            }
            int kp = kk * 8 + q;
            #pragma unroll
            for (int nt = 0; nt < 8; nt++) {
                int nn = nbase + nt * 8 + g;
                unsigned b0 = Bs[kp * BSTR + nn];
                unsigned b1 = Bs[(kp + 4) * BSTR + nn];
                mma16816(acc[0][nt], a[0], b0, b1);
                mma16816(acc[1][nt], a[1], b0, b1);
            }
        }
    }

    #pragma unroll
    for (int mt = 0; mt < 2; mt++) {
        #pragma unroll
        for (int h = 0; h < 2; h++) {
            int r = row0 + rbase + mt * 16 + g + h * 8;
            if (r < n) {
                #pragma unroll
                for (int nt = 0; nt < 8; nt++) {
                    int col = nbase + nt * 8 + q * 2;
                    float c0 = fmaxf(acc[mt][nt][h * 2] + bias[col], 0.f);
                    float c1 = fmaxf(acc[mt][nt][h * 2 + 1] + bias[col + 1], 0.f);
                    *(float2*)&H[(unsigned)r * 128 + col] = make_float2(c0, c1);
                }
            }
        }
    }
}

// ============ CSR gather: multi-edge warp loads (16B/lane) + fused BN stats ============
// Row = F fp16 = 16*F/8 bytes. Lane layout: sub = lane/LPR selects edge within group,
// fl = lane%LPR selects the 8-feature octet. Each warp-LDG covers EPG edges.
// m rows pre-scaled by dinv[row]; agg[node] = dinv[node] * sum m[row].
template <int F>
__global__ __launch_bounds__(256) void gather_kernel(const int* __restrict__ csr,
                                                     const int* __restrict__ offs,
                                                     const float* __restrict__ dinv,
                                                     const __half* __restrict__ m,
                                                     float* __restrict__ agg,
                                                     float* __restrict__ stats, int n) {
    constexpr int LPR = F / 8;        // lanes per row: 8 (F=64) or 16 (F=128)
    constexpr int EPG = 32 / LPR;     // edges per warp-load group: 4 or 2
    constexpr int NCH = 32 / (8 * EPG); // chunks of 8 groups per 32-edge window: 1 or 2
    __shared__ float ssum[F], ssq[F];
    if (threadIdx.x < F) { ssum[threadIdx.x] = 0.f; ssq[threadIdx.x] = 0.f; }
    __syncthreads();

    int node = (blockIdx.x * blockDim.x + threadIdx.x) >> 5;
    int lane = threadIdx.x & 31;
    int sub = lane / LPR;
    int fl  = lane % LPR;

    float acc[8];
    #pragma unroll
    for (int k = 0; k < 8; k++) acc[k] = 0.f;
    float out[8];
    #pragma unroll
    for (int k = 0; k < 8; k++) out[k] = 0.f;

    if (node < n) {
        int beg = offs[node], end = offs[node + 1];
        float dc = dinv[node];
        for (int i = beg; i < end; i += 32) {
            int idx = i + lane;
            int r = (idx < end) ? csr[idx] : 0;   // invalid lanes alias row 0 (L1-hot)
            int cnt = min(32, end - i);
            #pragma unroll
            for (int c = 0; c < NCH; c++) {
                if (c * 8 * EPG >= cnt) break;    // warp-uniform coarse skip
                uint4 w[8];
                float va[8];
                #pragma unroll
                for (int g = 0; g < 8; g++) {
                    int j = c * 8 * EPG + g * EPG + sub;
                    unsigned rr = (unsigned)__shfl_sync(0xffffffffu, r, j);
                    va[g] = (j < cnt) ? 1.f : 0.f;
                    w[g] = *(const uint4*)(m + rr * F + fl * 8);
                }
                #pragma unroll
                for (int g = 0; g < 8; g++) {
                    float2 a0 = __half22float2(*(__half2*)&w[g].x);
                    float2 a1 = __half22float2(*(__half2*)&w[g].y);
                    float2 a2 = __half22float2(*(__half2*)&w[g].z);
                    float2 a3 = __half22float2(*(__half2*)&w[g].w);
                    acc[0] = fmaf(va[g], a0.x, acc[0]);
                    acc[1] = fmaf(va[g], a0.y, acc[1]);
                    acc[2] = fmaf(va[g], a1.x, acc[2]);
                    acc[3] = fmaf(va[g], a1.y, acc[3]);
                    acc[4] = fmaf(va[g], a2.x, acc[4]);
                    acc[5] = fmaf(va[g], a2.y, acc[5]);
                    acc[6] = fmaf(va[g], a3.x, acc[6]);
                    acc[7] = fmaf(va[g], a3.y, acc[7]);
                }
            }
        }
        // reduce across sub-slots (lanes sharing the same feature octet)
        #pragma unroll
        for (int k = 0; k < 8; k++) {
            if (F == 64) acc[k] += __shfl_xor_sync(0xffffffffu, acc[k], 8);
            acc[k] += __shfl_xor_sync(0xffffffffu, acc[k], 16);
        }
        #pragma unroll
        for (int k = 0; k < 8; k++) out[k] = acc[k] * dc;
        if (sub == 0) {
            float* dst = &agg[(unsigned)node * F + fl * 8];
            *(float4*)dst       = make_float4(out[0], out[1], out[2], out[3]);
            *(float4*)(dst + 4) = make_float4(out[4], out[5], out[6], out[7]);
        }
    }

    // fused BN statistics: sub==0 lanes hold the node's feature octet
    if (sub == 0) {
        #pragma unroll
        for (int k = 0; k < 8; k++) {
            int ch = fl * 8 + k;
            atomicAdd(&ssum[ch], out[k]);
            atomicAdd(&ssq[ch], out[k] * out[k]);
        }
    }
    __syncthreads();
    if (threadIdx.x < F) {
        atomicAdd(&stats[threadIdx.x], ssum[threadIdx.x]);
        atomicAdd(&stats[F + threadIdx.x], ssq[threadIdx.x]);
    }
}

// a = gamma * rsqrt(var+eps); shift = beta - a*mu  (GCN bias cancels in BN)
__global__ void finalize_kernel(const float* __restrict__ stats, const float* __restrict__ g,
                                const float* __restrict__ be, float* __restrict__ ab,
                                int n, int F) {
    int c = threadIdx.x;
    if (c < F) {
        float inv_n = 1.f / (float)n;
        float mu = stats[c] * inv_n;
        float var = fmaxf(stats[F + c] * inv_n - mu * mu, 0.f);
        float a = g[c] * rsqrtf(var + 1e-5f);
        ab[c] = a;
        ab[F + c] = be[c] - a * mu;
    }
}

// ---------------- FC2 + softmax, one warp per node ----------------
__global__ void fc2_softmax_kernel(const float* __restrict__ H, const float* __restrict__ W2,
                                   const float* __restrict__ b2, float* __restrict__ out, int n) {
    int node = (blockIdx.x * blockDim.x + threadIdx.x) >> 5;
    int lane = threadIdx.x & 31;
    if (node >= n) return;
    float a0 = 0.f, a1 = 0.f;
    #pragma unroll
    for (int j = 0; j < 4; j++) {
        int k = lane + 32 * j;
        float h = H[(unsigned)node * 128 + k];
        a0 = fmaf(h, W2[k * 2 + 0], a0);
        a1 = fmaf(h, W2[k * 2 + 1], a1);
    }
    #pragma unroll
    for (int off = 16; off; off >>= 1) {
        a0 += __shfl_xor_sync(0xffffffffu, a0, off);
        a1 += __shfl_xor_sync(0xffffffffu, a1, off);
    }
    if (lane == 0) {
        float l0 = a0 + b2[0], l1 = a1 + b2[1];
        float mx = fmaxf(l0, l1);
        float e0 = expf(l0 - mx), e1 = expf(l1 - mx);
        float inv = 1.f / (e0 + e1);
        out[(size_t)node * 2 + 0] = l0;
        out[(size_t)node * 2 + 1] = l1;
        out[(size_t)2 * n + node * 2 + 0] = e0 * inv;
        out[(size_t)2 * n + node * 2 + 1] = e1 * inv;
    }
}

// ---------------- host launch (fork-join multi-stream, graph-capturable) ----------------
extern "C" void kernel_launch(void* const* d_in, const int* in_sizes, int n_in,
                              void* d_out, int out_size) {
    const float* x     = (const float*)d_in[0];
    const int*   ei[2] = {(const int*)d_in[1], (const int*)d_in[2]};
    const float* w0[2]   = {(const float*)d_in[3], (const float*)d_in[8]};
    const float* w1[2]   = {(const float*)d_in[5], (const float*)d_in[10]};
    const float* res1[2] = {(const float*)d_in[7], (const float*)d_in[12]};
    const float* bn_g0 = (const float*)d_in[13];
    const float* bn_b0 = (const float*)d_in[14];
    const float* bn_g1 = (const float*)d_in[15];
    const float* bn_b1 = (const float*)d_in[16];
    const float* fc1_w = (const float*)d_in[17];
    const float* fc1_b = (const float*)d_in[18];
    const float* fc2_w = (const float*)d_in[19];
    const float* fc2_b = (const float*)d_in[20];

    int n = in_sizes[0] / 64;
    int E = in_sizes[1] / 2;

    float *dinv_p[2], *agg0_p[2], *agg1_p[2], *proj_p[2];
    float *stats0_p[2], *stats1_p[2], *ab0_p[2], *ab1_p[2], *hfc_p;
    __half* m_p[2];
    int *deg_p[2], *offs_p[2], *cursor_p[2], *csr_p[2];
    {
        char* base;
        cudaGetSymbolAddress((void**)&base, g_dinv);
        dinv_p[0] = (float*)base; dinv_p[1] = dinv_p[0] + MAXN;
        cudaGetSymbolAddress((void**)&base, g_deg);
        deg_p[0] = (int*)base; deg_p[1] = deg_p[0] + MAXN;
        cudaGetSymbolAddress((void**)&base, g_offs);
        offs_p[0] = (int*)base; offs_p[1] = offs_p[0] + MAXNO;
        cudaGetSymbolAddress((void**)&base, g_cursor);
        cursor_p[0] = (int*)base; cursor_p[1] = cursor_p[0] + MAXN;
        cudaGetSymbolAddress((void**)&base, g_csr);
        csr_p[0] = (int*)base; csr_p[1] = csr_p[0] + MAXE;
        cudaGetSymbolAddress((void**)&base, g_m);
        m_p[0] = (__half*)base; m_p[1] = m_p[0] + (size_t)MAXN * 128;
        cudaGetSymbolAddress((void**)&base, g_agg0);
        agg0_p[0] = (float*)base; agg0_p[1] = agg0_p[0] + (size_t)MAXN * 64;
        cudaGetSymbolAddress((void**)&base, g_agg1);
        agg1_p[0] = (float*)base; agg1_p[1] = agg1_p[0] + (size_t)MAXN * 128;
        cudaGetSymbolAddress((void**)&base, g_proj);
        proj_p[0] = (float*)base; proj_p[1] = proj_p[0] + (size_t)MAXN * 128;
        cudaGetSymbolAddress((void**)&base, g_stats0);
        stats0_p[0] = (float*)base; stats0_p[1] = stats0_p[0] + 128;
        cudaGetSymbolAddress((void**)&base, g_stats1);
        stats1_p[0] = (float*)base; stats1_p[1] = stats1_p[0] + 256;
        cudaGetSymbolAddress((void**)&base, g_ab0);
        ab0_p[0] = (float*)base; ab0_p[1] = ab0_p[0] + 128;
        cudaGetSymbolAddress((void**)&base, g_ab1);
        ab1_p[0] = (float*)base; ab1_p[1] = ab1_p[0] + 256;
        cudaGetSymbolAddress((void**)&hfc_p, g_hfc);
    }

    int ebl = (E + 255) / 256;
    int hbl = (n + 127) / 128;  // hmma gemm blocks (128 rows/block)
    int wbl = (n + 7) / 8;      // warp-per-node blocks (8 warps/block)

    cudaEventRecord(g_ev[0], 0);

    for (int s = 0; s < 2; s++) {
        const int* row = ei[s];
        const int* col = row + E;
        cudaStream_t a = g_str[2 * s];
        cudaStream_t b = g_str[2 * s + 1];
        cudaEvent_t evScan = g_ev[1 + 5 * s];
        cudaEvent_t evFin0 = g_ev[2 + 5 * s];
        cudaEvent_t evProj = g_ev[3 + 5 * s];
        cudaEvent_t evDone = g_ev[4 + 5 * s];

        cudaStreamWaitEvent(a, g_ev[0], 0);
        cudaStreamWaitEvent(b, g_ev[0], 0);

        // stream a: degree -> scan (dinv) -> csr_fill
        cudaMemsetAsync(deg_p[s], 0, n * sizeof(int), a);
        deg_kernel<<<ebl, 256, 0, a>>>(col, deg_p[s], E);
        scan_kernel<<<1, 1024, 0, a>>>(deg_p[s], offs_p[s], cursor_p[s], dinv_p[s], n);
        cudaEventRecord(evScan, a);
        csr_fill_kernel<<<ebl, 256, 0, a>>>(row, col, cursor_p[s], csr_p[s], E);

        // stream b: stats zeroing + layer-0 HMMA GEMM (row-scaled fp16; waits on scan)
        cudaMemsetAsync(stats0_p[s], 0, 128 * sizeof(float), b);
        cudaMemsetAsync(stats1_p[s], 0, 256 * sizeof(float), b);
        cudaStreamWaitEvent(b, evScan, 0);
        hgemm_kernel<64, 0, 0><<<hbl, 256, 0, b>>>(x, nullptr, nullptr, w0[s],
                                                   dinv_p[s], m_p[s], n);
        cudaEventRecord(g_ev[5 + 5 * s], b);  // gemm0 done

        // join: gather layer 0 (fused BN stats), finalize BN0
        cudaStreamWaitEvent(a, g_ev[5 + 5 * s], 0);
        gather_kernel<64><<<wbl, 256, 0, a>>>(csr_p[s], offs_p[s], dinv_p[s], m_p[s],
                                              agg0_p[s], stats0_p[s], n);
        finalize_kernel<<<1, 64, 0, a>>>(stats0_p[s], bn_g0, bn_b0, ab0_p[s], n, 64);
        cudaEventRecord(evFin0, a);

        // layer 1: m = dinv*(h1' @ W1) fp16 on a; proj = h1' @ res1 fp32 on b
        hgemm_kernel<128, 1, 0><<<hbl, 256, 0, a>>>(agg0_p[s], x, ab0_p[s], w1[s],
                                                    dinv_p[s], m_p[s], n);
        cudaStreamWaitEvent(b, evFin0, 0);
        hgemm_kernel<128, 1, 1><<<hbl, 256, 0, b>>>(agg0_p[s], x, ab0_p[s], res1[s],
                                                    nullptr, proj_p[s], n);
        cudaEventRecord(evProj, b);

        gather_kernel<128><<<wbl, 256, 0, a>>>(csr_p[s], offs_p[s], dinv_p[s], m_p[s],
                                               agg1_p[s], stats1_p[s], n);
        finalize_kernel<<<1, 128, 0, a>>>(stats1_p[s], bn_g1, bn_b1, ab1_p[s], n, 128);
        cudaStreamWaitEvent(a, evProj, 0);
        cudaEventRecord(evDone, a);
    }

    // join both slices back to origin stream; head
    cudaStreamWaitEvent(0, g_ev[4], 0);
    cudaStreamWaitEvent(0, g_ev[9], 0);
    hfc1_kernel<<<hbl, 256>>>(agg1_p[0], proj_p[0], ab1_p[0],
                              agg1_p[1], proj_p[1], ab1_p[1],
                              fc1_w, fc1_b, hfc_p, n);
    fc2_softmax_kernel<<<wbl, 256>>>(hfc_p, fc2_w, fc2_b, (float*)d_out, n);
}

// round 10
// speedup vs baseline: 1.0751x; 1.0751x over previous
#include <cuda_runtime.h>
#include <cuda_bf16.h>
#include <cuda_fp16.h>
#include <math.h>

#define MAXN 50048           // divisible by 16
#define MAXNO (MAXN + 16)    // offs row stride
#define MAXE 1600000

// ---------------- per-slice device scratch (static; no allocations) ----------------
__device__ __align__(16) float  g_dinv[2][MAXN];
__device__ __align__(16) int    g_deg[2][MAXN];
__device__ __align__(16) int    g_offs[2][MAXNO];
__device__ __align__(16) int    g_cursor[2][MAXN];
__device__ __align__(16) int    g_csr[2][MAXE];
__device__ __align__(16) __half g_m[2][(size_t)MAXN * 128];     // fp16, pre-scaled by dinv[row]
__device__ __align__(16) float  g_agg0[2][(size_t)MAXN * 64];
__device__ __align__(16) float  g_agg1[2][(size_t)MAXN * 128];
__device__ __align__(16) float  g_proj[2][(size_t)MAXN * 128];
// per slice: [0,128) stats0 (sum,sq F=64); [128,384) stats1 (F=128); [384,386) int counters
__device__ __align__(16) float  g_stats[2][392];
__device__ __align__(16) float  g_ab0[2][128];
__device__ __align__(16) float  g_ab1[2][256];

// ---------------- static streams / events (host-side, created at load) ----------------
static cudaStream_t g_str[4];
static cudaEvent_t  g_ev[12];
static int g_init_streams = []() {
    int lo, hi;
    cudaDeviceGetStreamPriorityRange(&lo, &hi);
    for (int i = 0; i < 4; i++)
        cudaStreamCreateWithPriority(&g_str[i], cudaStreamNonBlocking, (i % 2 == 0) ? hi : lo);
    for (int i = 0; i < 12; i++) cudaEventCreateWithFlags(&g_ev[i], cudaEventDisableTiming);
    return 0;
}();

// nan_to_num(nan=0, posinf=100, neginf=-100)
__device__ __forceinline__ float san(float v) {
    if (isnan(v)) return 0.f;
    if (isinf(v)) return v > 0.f ? 100.f : -100.f;
    return v;
}

__device__ __forceinline__ unsigned h2u(__half2 h) { return *(unsigned*)&h; }

__device__ __forceinline__ float4 ldh4(const __half* p) {
    uint2 w = *(const uint2*)p;
    float2 a = __half22float2(*(__half2*)&w.x);
    float2 b = __half22float2(*(__half2*)&w.y);
    return make_float4(a.x, a.y, b.x, b.y);
}
__device__ __forceinline__ float2 ldh2(const __half* p) {
    return __half22float2(*(const __half2*)p);
}

// m16n8k16 f16xf16 -> f32 accumulate
__device__ __forceinline__ void mma16816(float* c, const unsigned* a, unsigned b0, unsigned b1) {
    asm volatile(
        "mma.sync.aligned.m16n8k16.row.col.f32.f16.f16.f32 "
        "{%0,%1,%2,%3}, {%4,%5,%6,%7}, {%8,%9}, {%0,%1,%2,%3};"
        : "+f"(c[0]), "+f"(c[1]), "+f"(c[2]), "+f"(c[3])
        : "r"(a[0]), "r"(a[1]), "r"(a[2]), "r"(a[3]), "r"(b0), "r"(b1));
}

// ---------------- degree ----------------
__global__ void deg_kernel(const int* __restrict__ col, int* __restrict__ deg, int E) {
    int e = blockIdx.x * blockDim.x + threadIdx.x;
    if (e < E) atomicAdd(&deg[col[e]], 1);
}

// single-block exclusive scan (x4 vectorized) -> offs/cursor + fused dinv = rsqrt(deg)
__global__ void scan_kernel(const int* __restrict__ deg, int* __restrict__ offs,
                            int* __restrict__ cursor, float* __restrict__ dinv, int n) {
    __shared__ int wsum[32];
    __shared__ int carry_s;
    int tid = threadIdx.x;
    int lane = tid & 31, wid = tid >> 5;
    if (tid == 0) carry_s = 0;
    __syncthreads();
    int nIter = (n + 4095) >> 12;
    for (int it = 0; it < nIter; it++) {
        int i0 = (it << 12) + tid * 4;
        int v0 = 0, v1 = 0, v2 = 0, v3 = 0;
        if (i0 + 3 < n) {
            int4 t = *(const int4*)(deg + i0);
            v0 = t.x; v1 = t.y; v2 = t.z; v3 = t.w;
        } else {
            if (i0 < n)     v0 = deg[i0];
            if (i0 + 1 < n) v1 = deg[i0 + 1];
            if (i0 + 2 < n) v2 = deg[i0 + 2];
            if (i0 + 3 < n) v3 = deg[i0 + 3];
        }
        int s = v0 + v1 + v2 + v3;
        int x = s;
        #pragma unroll
        for (int off = 1; off < 32; off <<= 1) {
            int y = __shfl_up_sync(0xffffffffu, x, off);
            if (lane >= off) x += y;
        }
        if (lane == 31) wsum[wid] = x;
        __syncthreads();
        if (wid == 0) {
            int w = wsum[lane];
            #pragma unroll
            for (int off = 1; off < 32; off <<= 1) {
                int y = __shfl_up_sync(0xffffffffu, w, off);
                if (lane >= off) w += y;
            }
            wsum[lane] = w;
        }
        __syncthreads();
        int pre = (wid > 0) ? wsum[wid - 1] : 0;
        int total = wsum[31];
        int e0 = carry_s + pre + x - s;
        int o1 = e0 + v0, o2 = o1 + v1, o3 = o2 + v2;
        if (i0 + 3 < n) {
            *(int4*)(offs + i0)   = make_int4(e0, o1, o2, o3);
            *(int4*)(cursor + i0) = make_int4(e0, o1, o2, o3);
            float4 dv = make_float4(v0 > 0 ? rsqrtf((float)v0) : 0.f,
                                    v1 > 0 ? rsqrtf((float)v1) : 0.f,
                                    v2 > 0 ? rsqrtf((float)v2) : 0.f,
                                    v3 > 0 ? rsqrtf((float)v3) : 0.f);
            *(float4*)(dinv + i0) = dv;
        } else {
            int oo[4] = {e0, o1, o2, o3};
            int vv[4] = {v0, v1, v2, v3};
            for (int j = 0; j < 4; j++) {
                if (i0 + j < n) {
                    offs[i0 + j] = oo[j];
                    cursor[i0 + j] = oo[j];
                    dinv[i0 + j] = vv[j] > 0 ? rsqrtf((float)vv[j]) : 0.f;
                }
            }
        }
        __syncthreads();
        if (tid == 0) carry_s += total;
        __syncthreads();
    }
    if (tid == 0) offs[n] = carry_s;
}

__global__ void csr_fill_kernel(const int* __restrict__ row, const int* __restrict__ col,
                                int* __restrict__ cursor, int* __restrict__ csr, int E) {
    int e = blockIdx.x * blockDim.x + threadIdx.x;
    if (e < E) {
        int pos = atomicAdd(&cursor[col[e]], 1);
        csr[pos] = row[e];
    }
}

// ================= HMMA GEMM: C[n,NOUT] = A'[n,64] @ B[64,NOUT] =================
// PRO: 0 = raw A; 1 = h1 epilogue: san(relu(ab[k]*A+ab[64+k]) + X)
// STO: 0 = fp16 * rs[row]; 1 = fp32
template <int NOUT, int PRO, int STO>
__global__ __launch_bounds__(256) void hgemm_kernel(const float* __restrict__ A,
                                                    const float* __restrict__ X,
                                                    const float* __restrict__ ab,
                                                    const float* __restrict__ B,
                                                    const float* __restrict__ rs,
                                                    void* __restrict__ C, int n) {
    constexpr int ASTR = 72;
    constexpr int BSTR = NOUT + 8;
    __shared__ __half  As[128 * ASTR];
    __shared__ unsigned Bs[32 * BSTR];

    int tid = threadIdx.x;
    int row0 = blockIdx.x * 128;

    #pragma unroll
    for (int i = 0; i < 16; i++) {
        int idx = tid + 256 * i;
        int r = idx >> 5, kp = idx & 31;
        float v0 = 0.f, v1 = 0.f;
        if (row0 + r < n) {
            unsigned o = (unsigned)(row0 + r) * 64u + kp * 2;
            if (PRO == 1) {
                float2 av = *(const float2*)&A[o];
                float2 xv = *(const float2*)&X[o];
                float t0 = fmaf(ab[kp * 2], av.x, ab[64 + kp * 2]);
                float t1 = fmaf(ab[kp * 2 + 1], av.y, ab[64 + kp * 2 + 1]);
                v0 = san(fmaxf(t0, 0.f) + xv.x);
                v1 = san(fmaxf(t1, 0.f) + xv.y);
            } else {
                float2 av = *(const float2*)&A[o];
                v0 = av.x; v1 = av.y;
            }
        }
        *(unsigned*)&As[r * ASTR + kp * 2] = h2u(__floats2half2_rn(v0, v1));
    }
    constexpr int BW = (32 * NOUT) / 256;
    #pragma unroll
    for (int i = 0; i < BW; i++) {
        int idx = tid + 256 * i;
        int kp = idx / NOUT, nn = idx % NOUT;
        Bs[kp * BSTR + nn] = h2u(__floats2half2_rn(B[(2 * kp) * NOUT + nn],
                                                   B[(2 * kp + 1) * NOUT + nn]));
    }
    __syncthreads();

    int warp = tid >> 5, lane = tid & 31;
    constexpr int NT = NOUT / 16;
    int wr = warp >> 1, wc = warp & 1;
    int rbase = wr * 32, nbase = wc * (NOUT / 2);
    int g = lane >> 2, q = lane & 3;

    float acc[2][NT][4];
    #pragma unroll
    for (int mt = 0; mt < 2; mt++)
        #pragma unroll
        for (int nt = 0; nt < NT; nt++)
            #pragma unroll
            for (int e = 0; e < 4; e++) acc[mt][nt][e] = 0.f;

    #pragma unroll
    for (int kk = 0; kk < 4; kk++) {
        unsigned a[2][4];
        #pragma unroll
        for (int mt = 0; mt < 2; mt++) {
            const __half* ap = &As[(rbase + mt * 16 + g) * ASTR + kk * 16 + q * 2];
            a[mt][0] = *(const unsigned*)ap;
            a[mt][1] = *(const unsigned*)(ap + 8 * ASTR);
            a[mt][2] = *(const unsigned*)(ap + 8);
            a[mt][3] = *(const unsigned*)(ap + 8 * ASTR + 8);
        }
        int kp = kk * 8 + q;
        #pragma unroll
        for (int nt = 0; nt < NT; nt++) {
            int nn = nbase + nt * 8 + g;
            unsigned b0 = Bs[kp * BSTR + nn];
            unsigned b1 = Bs[(kp + 4) * BSTR + nn];
            mma16816(acc[0][nt], a[0], b0, b1);
            mma16816(acc[1][nt], a[1], b0, b1);
        }
    }

    #pragma unroll
    for (int mt = 0; mt < 2; mt++) {
        #pragma unroll
        for (int h = 0; h < 2; h++) {
            int r = row0 + rbase + mt * 16 + g + h * 8;
            if (r < n) {
                float sc = (STO == 0) ? rs[r] : 1.f;
                #pragma unroll
                for (int nt = 0; nt < NT; nt++) {
                    float c0 = acc[mt][nt][h * 2], c1 = acc[mt][nt][h * 2 + 1];
                    int col = nbase + nt * 8 + q * 2;
                    if (STO == 0) {
                        *(unsigned*)&((__half*)C)[(unsigned)r * NOUT + col] =
                            h2u(__floats2half2_rn(c0 * sc, c1 * sc));
                    } else {
                        *(float2*)&((float*)C)[(unsigned)r * NOUT + col] = make_float2(c0, c1);
                    }
                }
            }
        }
    }
}

// ====== FC1+FC2+softmax fused: per 128-row block computes full head ======
__global__ __launch_bounds__(256) void head_kernel(const float* __restrict__ agg0,
                                                   const float* __restrict__ proj0,
                                                   const float* __restrict__ ab_0,
                                                   const float* __restrict__ agg1,
                                                   const float* __restrict__ proj1,
                                                   const float* __restrict__ ab_1,
                                                   const float* __restrict__ B,
                                                   const float* __restrict__ bias,
                                                   const float* __restrict__ W2,
                                                   const float* __restrict__ b2,
                                                   float* __restrict__ out, int n) {
    constexpr int ASTR = 72;
    constexpr int BSTR = 136;
    __shared__ __half  As[128 * ASTR];
    __shared__ unsigned Bs[32 * BSTR];
    __shared__ float slog[256];   // [row_local][2] logit partials

    int tid = threadIdx.x;
    int row0 = blockIdx.x * 128;
    int warp = tid >> 5, lane = tid & 31;
    int wr = warp >> 1, wc = warp & 1;
    int rbase = wr * 32, nbase = wc * 64;
    int g = lane >> 2, q = lane & 3;

    if (tid < 256) slog[tid] = 0.f;

    float acc[2][8][4];
    #pragma unroll
    for (int mt = 0; mt < 2; mt++)
        #pragma unroll
        for (int nt = 0; nt < 8; nt++)
            #pragma unroll
            for (int e = 0; e < 4; e++) acc[mt][nt][e] = 0.f;

    for (int c = 0; c < 4; c++) {
        __syncthreads();
        const float* agg = (c < 2) ? agg0 : agg1;
        const float* prj = (c < 2) ? proj0 : proj1;
        const float* ab  = (c < 2) ? ab_0 : ab_1;
        int kbase = (c & 1) * 64;
        #pragma unroll
        for (int i = 0; i < 16; i++) {
            int idx = tid + 256 * i;
            int r = idx >> 5, kp = idx & 31;
            float v0 = 0.f, v1 = 0.f;
            if (row0 + r < n) {
                int ch = kbase + kp * 2;
                unsigned o = (unsigned)(row0 + r) * 128u + ch;
                float2 av = *(const float2*)&agg[o];
                float2 pv = *(const float2*)&prj[o];
                v0 = san(fmaf(ab[ch], av.x, ab[128 + ch]) + pv.x);
                v1 = san(fmaf(ab[ch + 1], av.y, ab[128 + ch + 1]) + pv.y);
            }
            *(unsigned*)&As[r * ASTR + kp * 2] = h2u(__floats2half2_rn(v0, v1));
        }
        const float* Bc = B + c * 64 * 128;
        #pragma unroll
        for (int i = 0; i < 16; i++) {
            int idx = tid + 256 * i;
            int kp = idx >> 7, nn = idx & 127;
            Bs[kp * BSTR + nn] = h2u(__floats2half2_rn(Bc[(2 * kp) * 128 + nn],
                                                       Bc[(2 * kp + 1) * 128 + nn]));
        }
        __syncthreads();

        #pragma unroll
        for (int kk = 0; kk < 4; kk++) {
            unsigned a[2][4];
            #pragma unroll
            for (int mt = 0; mt < 2; mt++) {
                const __half* ap = &As[(rbase + mt * 16 + g) * ASTR + kk * 16 + q * 2];
                a[mt][0] = *(const unsigned*)ap;
                a[mt][1] = *(const unsigned*)(ap + 8 * ASTR);
                a[mt][2] = *(const unsigned*)(ap + 8);
                a[mt][3] = *(const unsigned*)(ap + 8 * ASTR + 8);
            }
            int kp = kk * 8 + q;
            #pragma unroll
            for (int nt = 0; nt < 8; nt++) {
                int nn = nbase + nt * 8 + g;
                unsigned b0 = Bs[kp * BSTR + nn];
                unsigned b1 = Bs[(kp + 4) * BSTR + nn];
                mma16816(acc[0][nt], a[0], b0, b1);
                mma16816(acc[1][nt], a[1], b0, b1);
            }
        }
    }
    __syncthreads();

    // fc2 partials: h = relu(acc + bias); accumulate h*W2 into shared per-row logits
    #pragma unroll
    for (int mt = 0; mt < 2; mt++) {
        #pragma unroll
        for (int h = 0; h < 2; h++) {
            int rl = rbase + mt * 16 + g + h * 8;
            float l0 = 0.f, l1 = 0.f;
            #pragma unroll
            for (int nt = 0; nt < 8; nt++) {
                int col = nbase + nt * 8 + q * 2;
                float h0 = fmaxf(acc[mt][nt][h * 2] + bias[col], 0.f);
                float h1 = fmaxf(acc[mt][nt][h * 2 + 1] + bias[col + 1], 0.f);
                l0 = fmaf(h0, W2[col * 2],     fmaf(h1, W2[(col + 1) * 2],     l0));
                l1 = fmaf(h0, W2[col * 2 + 1], fmaf(h1, W2[(col + 1) * 2 + 1], l1));
            }
            atomicAdd(&slog[rl * 2],     l0);
            atomicAdd(&slog[rl * 2 + 1], l1);
        }
    }
    __syncthreads();

    if (tid < 128) {
        int r = row0 + tid;
        if (r < n) {
            float l0 = slog[tid * 2] + b2[0];
            float l1 = slog[tid * 2 + 1] + b2[1];
            float mx = fmaxf(l0, l1);
            float e0 = expf(l0 - mx), e1 = expf(l1 - mx);
            float inv = 1.f / (e0 + e1);
            *(float2*)&out[(size_t)r * 2] = make_float2(l0, l1);
            *(float2*)&out[(size_t)2 * n + r * 2] = make_float2(e0 * inv, e1 * inv);
        }
    }
}

// ===== CSR gather (R8 form) + fused BN stats + fused last-block finalize =====
// m rows pre-scaled by dinv[row]; agg[node] = dinv[node]*sum m[row].
// Last block computes ab[] = {gamma*rsqrt(var+eps), beta - a*mu} from stats.
template <int F>
__global__ __launch_bounds__(256) void gather_kernel(const int* __restrict__ csr,
                                                     const int* __restrict__ offs,
                                                     const float* __restrict__ dinv,
                                                     const __half* __restrict__ m,
                                                     float* __restrict__ agg,
                                                     float* __restrict__ stats,
                                                     int* __restrict__ ctr,
                                                     const float* __restrict__ gam,
                                                     const float* __restrict__ bet,
                                                     float* __restrict__ ab, int n) {
    constexpr int VEC = F / 32;  // 2 or 4
    __shared__ float ssum[F], ssq[F];
    __shared__ int isLast;
    if (threadIdx.x < F) { ssum[threadIdx.x] = 0.f; ssq[threadIdx.x] = 0.f; }
    __syncthreads();

    int node = (blockIdx.x * blockDim.x + threadIdx.x) >> 5;
    int lane = threadIdx.x & 31;
    float acc[VEC];
    #pragma unroll
    for (int v = 0; v < VEC; v++) acc[v] = 0.f;
    float out[VEC];
    #pragma unroll
    for (int v = 0; v < VEC; v++) out[v] = 0.f;

    if (node < n) {
        int beg = offs[node], end = offs[node + 1];
        float dc = dinv[node];
        for (int i = beg; i < end; i += 32) {
            int idx = i + lane;
            int r = (idx < end) ? csr[idx] : 0;
            int cnt = min(32, end - i);
            int j = 0;
            for (; j + 8 <= cnt; j += 8) {
                unsigned rr[8];
                #pragma unroll
                for (int t = 0; t < 8; t++)
                    rr[t] = (unsigned)__shfl_sync(0xffffffffu, r, j + t);
                if (VEC == 4) {
                    float4 v[8];
                    #pragma unroll
                    for (int t = 0; t < 8; t++) v[t] = ldh4(m + rr[t] * F + lane * 4);
                    #pragma unroll
                    for (int t = 0; t < 8; t++) {
                        acc[0] += v[t].x; acc[1] += v[t].y;
                        acc[2] += v[t].z; acc[3] += v[t].w;
                    }
                } else {
                    float2 v[8];
                    #pragma unroll
                    for (int t = 0; t < 8; t++) v[t] = ldh2(m + rr[t] * F + lane * 2);
                    #pragma unroll
                    for (int t = 0; t < 8; t++) {
                        acc[0] += v[t].x; acc[1] += v[t].y;
                    }
                }
            }
            for (; j < cnt; j++) {
                unsigned rr = (unsigned)__shfl_sync(0xffffffffu, r, j);
                if (VEC == 4) {
                    float4 v = ldh4(m + rr * F + lane * 4);
                    acc[0] += v.x; acc[1] += v.y; acc[2] += v.z; acc[3] += v.w;
                } else {
                    float2 v = ldh2(m + rr * F + lane * 2);
                    acc[0] += v.x; acc[1] += v.y;
                }
            }
        }
        #pragma unroll
        for (int v = 0; v < VEC; v++) out[v] = acc[v] * dc;
        if (VEC == 4)
            *(float4*)&agg[(unsigned)node * F + lane * 4] = make_float4(out[0], out[1], out[2], out[3]);
        else
            *(float2*)&agg[(unsigned)node * F + lane * 2] = make_float2(out[0], out[1]);
    }

    // fused BN statistics: block-reduce then one global atomic per channel
    #pragma unroll
    for (int v = 0; v < VEC; v++) {
        int c = lane * VEC + v;
        atomicAdd(&ssum[c], out[v]);
        atomicAdd(&ssq[c], out[v] * out[v]);
    }
    __syncthreads();
    if (threadIdx.x < F) {
        atomicAdd(&stats[threadIdx.x], ssum[threadIdx.x]);
        atomicAdd(&stats[F + threadIdx.x], ssq[threadIdx.x]);
    }

    // last block computes ab (finalize fused)
    __threadfence();
    __syncthreads();
    if (threadIdx.x == 0)
        isLast = (atomicAdd(ctr, 1) == (int)gridDim.x - 1) ? 1 : 0;
    __syncthreads();
    if (isLast && threadIdx.x < F) {
        int c = threadIdx.x;
        float inv_n = 1.f / (float)n;
        float su = __ldcg(&stats[c]);
        float sq = __ldcg(&stats[F + c]);
        float mu = su * inv_n;
        float var = fmaxf(sq * inv_n - mu * mu, 0.f);
        float a = gam[c] * rsqrtf(var + 1e-5f);
        ab[c] = a;
        ab[F + c] = bet[c] - a * mu;
    }
}

// ---------------- host launch (fork-join multi-stream, graph-capturable) ----------------
extern "C" void kernel_launch(void* const* d_in, const int* in_sizes, int n_in,
                              void* d_out, int out_size) {
    const float* x     = (const float*)d_in[0];
    const int*   ei[2] = {(const int*)d_in[1], (const int*)d_in[2]};
    const float* w0[2]   = {(const float*)d_in[3], (const float*)d_in[8]};
    const float* w1[2]   = {(const float*)d_in[5], (const float*)d_in[10]};
    const float* res1[2] = {(const float*)d_in[7], (const float*)d_in[12]};
    const float* bn_g0 = (const float*)d_in[13];
    const float* bn_b0 = (const float*)d_in[14];
    const float* bn_g1 = (const float*)d_in[15];
    const float* bn_b1 = (const float*)d_in[16];
    const float* fc1_w = (const float*)d_in[17];
    const float* fc1_b = (const float*)d_in[18];
    const float* fc2_w = (const float*)d_in[19];
    const float* fc2_b = (const float*)d_in[20];

    int n = in_sizes[0] / 64;
    int E = in_sizes[1] / 2;

    float *dinv_p[2], *agg0_p[2], *agg1_p[2], *proj_p[2];
    float *stats_p[2], *ab0_p[2], *ab1_p[2];
    int   *ctr_p[2];
    __half* m_p[2];
    int *deg_p[2], *offs_p[2], *cursor_p[2], *csr_p[2];
    {
        char* base;
        cudaGetSymbolAddress((void**)&base, g_dinv);
        dinv_p[0] = (float*)base; dinv_p[1] = dinv_p[0] + MAXN;
        cudaGetSymbolAddress((void**)&base, g_deg);
        deg_p[0] = (int*)base; deg_p[1] = deg_p[0] + MAXN;
        cudaGetSymbolAddress((void**)&base, g_offs);
        offs_p[0] = (int*)base; offs_p[1] = offs_p[0] + MAXNO;
        cudaGetSymbolAddress((void**)&base, g_cursor);
        cursor_p[0] = (int*)base; cursor_p[1] = cursor_p[0] + MAXN;
        cudaGetSymbolAddress((void**)&base, g_csr);
        csr_p[0] = (int*)base; csr_p[1] = csr_p[0] + MAXE;
        cudaGetSymbolAddress((void**)&base, g_m);
        m_p[0] = (__half*)base; m_p[1] = m_p[0] + (size_t)MAXN * 128;
        cudaGetSymbolAddress((void**)&base, g_agg0);
        agg0_p[0] = (float*)base; agg0_p[1] = agg0_p[0] + (size_t)MAXN * 64;
        cudaGetSymbolAddress((void**)&base, g_agg1);
        agg1_p[0] = (float*)base; agg1_p[1] = agg1_p[0] + (size_t)MAXN * 128;
        cudaGetSymbolAddress((void**)&base, g_proj);
        proj_p[0] = (float*)base; proj_p[1] = proj_p[0] + (size_t)MAXN * 128;
        cudaGetSymbolAddress((void**)&base, g_stats);
        stats_p[0] = (float*)base; stats_p[1] = stats_p[0] + 392;
        ctr_p[0] = (int*)(stats_p[0] + 384);
        ctr_p[1] = (int*)(stats_p[1] + 384);
        cudaGetSymbolAddress((void**)&base, g_ab0);
        ab0_p[0] = (float*)base; ab0_p[1] = ab0_p[0] + 128;
        cudaGetSymbolAddress((void**)&base, g_ab1);
        ab1_p[0] = (float*)base; ab1_p[1] = ab1_p[0] + 256;
    }

    int ebl = (E + 255) / 256;
    int hbl = (n + 127) / 128;  // hmma gemm blocks (128 rows/block)
    int wbl = (n + 7) / 8;      // warp-per-node blocks (8 warps/block)

    cudaEventRecord(g_ev[0], 0);

    for (int s = 0; s < 2; s++) {
        const int* row = ei[s];
        const int* col = row + E;
        cudaStream_t a = g_str[2 * s];       // high priority
        cudaStream_t b = g_str[2 * s + 1];
        cudaEvent_t evScan = g_ev[1 + 5 * s];
        cudaEvent_t evFin0 = g_ev[2 + 5 * s];
        cudaEvent_t evProj = g_ev[3 + 5 * s];
        cudaEvent_t evDone = g_ev[4 + 5 * s];
        cudaEvent_t evG0   = g_ev[5 + 5 * s];

        cudaStreamWaitEvent(a, g_ev[0], 0);
        cudaStreamWaitEvent(b, g_ev[0], 0);

        // stream a: degree -> scan (dinv) -> csr_fill
        cudaMemsetAsync(deg_p[s], 0, n * sizeof(int), a);
        deg_kernel<<<ebl, 256, 0, a>>>(col, deg_p[s], E);
        scan_kernel<<<1, 1024, 0, a>>>(deg_p[s], offs_p[s], cursor_p[s], dinv_p[s], n);
        cudaEventRecord(evScan, a);
        csr_fill_kernel<<<ebl, 256, 0, a>>>(row, col, cursor_p[s], csr_p[s], E);

        // stream b: stats+ctr zeroing + layer-0 HMMA GEMM (row-scaled fp16; waits on scan)
        cudaMemsetAsync(stats_p[s], 0, 392 * sizeof(float), b);
        cudaStreamWaitEvent(b, evScan, 0);
        hgemm_kernel<64, 0, 0><<<hbl, 256, 0, b>>>(x, nullptr, nullptr, w0[s],
                                                   dinv_p[s], m_p[s], n);
        cudaEventRecord(evG0, b);

        // join: gather layer 0 (fused BN stats + finalize -> ab0)
        cudaStreamWaitEvent(a, evG0, 0);
        gather_kernel<64><<<wbl, 256, 0, a>>>(csr_p[s], offs_p[s], dinv_p[s], m_p[s],
                                              agg0_p[s], stats_p[s], ctr_p[s],
                                              bn_g0, bn_b0, ab0_p[s], n);
        cudaEventRecord(evFin0, a);

        // layer 1: m = dinv*(h1' @ W1) fp16 on a; proj = h1' @ res1 fp32 on b
        hgemm_kernel<128, 1, 0><<<hbl, 256, 0, a>>>(agg0_p[s], x, ab0_p[s], w1[s],
                                                    dinv_p[s], m_p[s], n);
        cudaStreamWaitEvent(b, evFin0, 0);
        hgemm_kernel<128, 1, 1><<<hbl, 256, 0, b>>>(agg0_p[s], x, ab0_p[s], res1[s],
                                                    nullptr, proj_p[s], n);
        cudaEventRecord(evProj, b);

        // gather layer 1 (fused BN stats + finalize -> ab1)
        gather_kernel<128><<<wbl, 256, 0, a>>>(csr_p[s], offs_p[s], dinv_p[s], m_p[s],
                                               agg1_p[s], stats_p[s] + 128, ctr_p[s] + 1,
                                               bn_g1, bn_b1, ab1_p[s], n);
        cudaStreamWaitEvent(a, evProj, 0);
        cudaEventRecord(evDone, a);
    }

    // join both slices back to origin stream; fused head (fc1+fc2+softmax)
    cudaStreamWaitEvent(0, g_ev[4], 0);
    cudaStreamWaitEvent(0, g_ev[9], 0);
    head_kernel<<<hbl, 256>>>(agg1_p[0], proj_p[0], ab1_p[0],
                              agg1_p[1], proj_p[1], ab1_p[1],
                              fc1_w, fc1_b, fc2_w, fc2_b, (float*)d_out, n);
}